// round 1
// baseline (speedup 1.0000x reference)
#include <cuda_runtime.h>
#include <math_constants.h>

// Problem constants
#define B_  4
#define T_  1024
#define M_  4096          // B*T tokens
#define H_  2048
#define V_  32000
// GEMM tiling
#define TM  128
#define TN  128
#define KB  8
#define KT  (H_/KB)       // 256 k-steps
#define NT  (V_/TN)       // 250 vocab tiles
#define MT  (M_/TM)       // 32 token tiles
#define LDA 132           // padded smem row stride (floats)
#define LDB 132

// ---------------- scratch (no allocations allowed) ----------------
__device__ int   g_is64;
__device__ float g_pmax[(size_t)M_ * NT];   // per (token, vocab-tile) max
__device__ float g_psum[(size_t)M_ * NT];   // per (token, vocab-tile) sum exp
__device__ float g_tok [M_];                // logit of the target token (incl. bias)
__device__ float g_losspt[M_];
__device__ float g_klpt  [M_];
__device__ float g_clippt[M_];
__device__ float g_maskpt[M_];

// ---------------- kernel 0: detect int32 vs int64 input_id ----------------
// If input_id is int64 (little-endian, values in [0,32000)), every odd int32
// word of the buffer is 0. For genuine int32 ids that is astronomically
// unlikely over 2048 samples. Reads only the first 4096 int32 words, which is
// in-bounds for both layouts.
__global__ void detect_id64_kernel(const int* __restrict__ idw) {
    __shared__ int bad;
    if (threadIdx.x == 0) bad = 0;
    __syncthreads();
    int local = 0;
    for (int i = threadIdx.x; i < 2048; i += blockDim.x)
        if (idw[2 * i + 1] != 0) local = 1;
    if (local) atomicOr(&bad, 1);
    __syncthreads();
    if (threadIdx.x == 0) g_is64 = bad ? 0 : 1;
}

// ---------------- kernel 1: tiled GEMM + streaming LSE partials ----------------
// C[m, n] = x[m, :] . W[n, :] + bias[n], never materialized; per 128x128 tile
// we emit (rowmax, rowsumexp) partials and gather the target-token logit.
__global__ __launch_bounds__(256, 2)
void gemm_lse_kernel(const float* __restrict__ X, const float* __restrict__ W,
                     const float* __restrict__ bias, const void* __restrict__ idptr)
{
    const int tileM = blockIdx.x, tileN = blockIdx.y;
    const int m0 = tileM * TM, n0 = tileN * TN;
    const int tid = threadIdx.x;
    const int tx = tid & 15, ty = tid >> 4;

    __shared__ __align__(16) float As[2][KB][LDA];
    __shared__ __align__(16) float Bs[2][KB][LDB];

    float acc[8][8];
#pragma unroll
    for (int i = 0; i < 8; i++)
#pragma unroll
        for (int j = 0; j < 8; j++) acc[i][j] = 0.f;

    // global->shared staging: 256 threads move 128 rows x 8 floats per operand
    const int lrow = tid >> 1;         // 0..127
    const int lk   = (tid & 1) * 4;    // 0 or 4
    const float* Xp = X + (size_t)(m0 + lrow) * H_ + lk;
    const float* Wp = W + (size_t)(n0 + lrow) * H_ + lk;

    {   // stage 0
        float4 av = *(const float4*)Xp;
        float4 bv = *(const float4*)Wp;
        As[0][lk+0][lrow]=av.x; As[0][lk+1][lrow]=av.y; As[0][lk+2][lrow]=av.z; As[0][lk+3][lrow]=av.w;
        Bs[0][lk+0][lrow]=bv.x; Bs[0][lk+1][lrow]=bv.y; Bs[0][lk+2][lrow]=bv.z; Bs[0][lk+3][lrow]=bv.w;
    }
    __syncthreads();

    for (int kt = 0; kt < KT; ++kt) {
        const int cur = kt & 1;
        float4 an, bn;
        if (kt + 1 < KT) {
            an = *(const float4*)(Xp + (size_t)(kt + 1) * KB);
            bn = *(const float4*)(Wp + (size_t)(kt + 1) * KB);
        }
#pragma unroll
        for (int k = 0; k < KB; k++) {
            // micro-tile split 4+4 at +64 keeps LDS.128 conflict-free
            float4 a0 = *(const float4*)&As[cur][k][ty * 4];
            float4 a1 = *(const float4*)&As[cur][k][64 + ty * 4];
            float4 b0 = *(const float4*)&Bs[cur][k][tx * 4];
            float4 b1 = *(const float4*)&Bs[cur][k][64 + tx * 4];
            float a[8] = {a0.x,a0.y,a0.z,a0.w,a1.x,a1.y,a1.z,a1.w};
            float b[8] = {b0.x,b0.y,b0.z,b0.w,b1.x,b1.y,b1.z,b1.w};
#pragma unroll
            for (int i = 0; i < 8; i++)
#pragma unroll
                for (int j = 0; j < 8; j++)
                    acc[i][j] = fmaf(a[i], b[j], acc[i][j]);
        }
        if (kt + 1 < KT) {
            const int nxt = cur ^ 1;
            As[nxt][lk+0][lrow]=an.x; As[nxt][lk+1][lrow]=an.y; As[nxt][lk+2][lrow]=an.z; As[nxt][lk+3][lrow]=an.w;
            Bs[nxt][lk+0][lrow]=bn.x; Bs[nxt][lk+1][lrow]=bn.y; Bs[nxt][lk+2][lrow]=bn.z; Bs[nxt][lk+3][lrow]=bn.w;
            __syncthreads();
        }
    }

    // ---- epilogue: bias add, per-row (max, sumexp) across this 128-col tile ----
    const bool is64 = (g_is64 != 0);
    float bj[8];
#pragma unroll
    for (int j = 0; j < 8; j++) {
        int col = (j < 4) ? (tx * 4 + j) : (64 + tx * 4 + j - 4);
        bj[j] = bias[n0 + col];
    }
#pragma unroll
    for (int i = 0; i < 8; i++) {
        const int row = m0 + ((i < 4) ? (ty * 4 + i) : (64 + ty * 4 + i - 4));
        float v[8];
        float mx = -CUDART_INF_F;
#pragma unroll
        for (int j = 0; j < 8; j++) { v[j] = acc[i][j] + bj[j]; mx = fmaxf(mx, v[j]); }
        // reduce across the 16 tx-lanes of this half-warp (same row set)
#pragma unroll
        for (int o = 8; o; o >>= 1) mx = fmaxf(mx, __shfl_xor_sync(0xffffffffu, mx, o));
        float s = 0.f;
#pragma unroll
        for (int j = 0; j < 8; j++) s += expf(v[j] - mx);
#pragma unroll
        for (int o = 8; o; o >>= 1) s += __shfl_xor_sync(0xffffffffu, s, o);
        if (tx == 0) {
            g_pmax[(size_t)row * NT + tileN] = mx;
            g_psum[(size_t)row * NT + tileN] = s;
        }
        // gather target-token logit (exactly one CTA/thread matches per row)
        const int vid = is64 ? (int)((const long long*)idptr)[row]
                             : ((const int*)idptr)[row];
        const int local = vid - n0;
        if (local >= 0 && local < TN) {
#pragma unroll
            for (int j = 0; j < 8; j++) {
                int col = (j < 4) ? (tx * 4 + j) : (64 + tx * 4 + j - 4);
                if (col == local) g_tok[row] = v[j];
            }
        }
    }
}

// ---------------- kernel 2: combine partials, per-token GRPO terms ----------------
__global__ void combine_kernel(const int* __restrict__ amask,
                               const float* __restrict__ adv,
                               const float* __restrict__ ref,
                               const float* __restrict__ oldlp,
                               float* __restrict__ out)
{
    const int warp = threadIdx.x >> 5;
    const int lane = threadIdx.x & 31;
    const int t = blockIdx.x * 8 + warp;     // token id
    if (t >= M_) return;

    const float* pm = g_pmax + (size_t)t * NT;
    const float* ps = g_psum + (size_t)t * NT;
    float M = -CUDART_INF_F;
    for (int j = lane; j < NT; j += 32) M = fmaxf(M, pm[j]);
#pragma unroll
    for (int o = 16; o; o >>= 1) M = fmaxf(M, __shfl_xor_sync(0xffffffffu, M, o));
    float S = 0.f;
    for (int j = lane; j < NT; j += 32) S += ps[j] * expf(pm[j] - M);
#pragma unroll
    for (int o = 16; o; o >>= 1) S += __shfl_xor_sync(0xffffffffu, S, o);

    if (lane == 0) {
        const float lse  = M + logf(S);
        const float logp = g_tok[t] - lse;
        out[1 + t] = logp;                                  // per_token_logps

        const float mask = (float)amask[t];
        const float a    = adv[t / T_];
        const float d    = ref[t] - logp;
        const float kl   = expf(d) - d - 1.f;
        const float c1   = expf(logp - oldlp[t]);
        const float c2   = fminf(fmaxf(c1, 0.8f), 1.2f);    // eps = 0.2
        const float l1   = c1 * a, l2 = c2 * a;
        const float ptl  = -(fminf(l1, l2) - 0.04f * kl);   // beta = 0.04
        g_losspt[t] = ptl * mask;
        g_klpt  [t] = kl  * mask;
        g_clippt[t] = (l1 < l2 ? 1.f : 0.f) * mask;
        g_maskpt[t] = mask;
    }
}

// ---------------- kernel 3: deterministic final reductions ----------------
__global__ void finalize_kernel(float* __restrict__ out, int out_size)
{
    __shared__ float sl[1024], sk[1024], sc[1024], sm[1024];
    const int t = threadIdx.x;
    float l = 0.f, k = 0.f, c = 0.f, m = 0.f;
    for (int i = t; i < M_; i += 1024) {
        l += g_losspt[i]; k += g_klpt[i]; c += g_clippt[i]; m += g_maskpt[i];
    }
    sl[t] = l; sk[t] = k; sc[t] = c; sm[t] = m;
    __syncthreads();
    for (int s = 512; s; s >>= 1) {
        if (t < s) { sl[t]+=sl[t+s]; sk[t]+=sk[t+s]; sc[t]+=sc[t+s]; sm[t]+=sm[t+s]; }
        __syncthreads();
    }
    if (t == 0) {
        out[0]      = sl[0] / sm[0];   // loss
        out[M_ + 1] = sk[0] / sm[0];   // mean_kl
        out[M_ + 2] = sc[0] / sm[0];   // clip_ratio
    }
    // defensively clear any padding the harness may have allocated
    for (int i = M_ + 3 + t; i < out_size; i += 1024) out[i] = 0.f;
}

// ---------------- launch ----------------
extern "C" void kernel_launch(void* const* d_in, const int* in_sizes, int n_in,
                              void* d_out, int out_size)
{
    const float* x     = (const float*)d_in[0];
    const float* w     = (const float*)d_in[1];
    const float* bias  = (const float*)d_in[2];
    const void*  ids   = d_in[3];
    const int*   amask = (const int*)d_in[4];
    const float* adv   = (const float*)d_in[5];
    const float* ref   = (const float*)d_in[6];
    const float* oldlp = (const float*)d_in[7];
    float* out = (float*)d_out;

    detect_id64_kernel<<<1, 256>>>((const int*)ids);

    dim3 grid(MT, NT);                 // x = token tiles (fast) -> W-tile L2 reuse
    gemm_lse_kernel<<<grid, 256>>>(x, w, bias, ids);

    combine_kernel<<<M_ / 8, 256>>>(amask, adv, ref, oldlp, out);
    finalize_kernel<<<1, 1024>>>(out, out_size);
}

// round 4
// speedup vs baseline: 1.1714x; 1.1714x over previous
#include <cuda_runtime.h>
#include <math_constants.h>
#include <cstdint>

// ---------------- problem constants ----------------
#define B_  4
#define T_  1024
#define M_  4096          // B*T tokens
#define H_  2048
#define V_  32000

// ---------------- GEMM tiling ----------------
#define TM  128           // CTA M tile
#define TN  256           // CTA N tile
#define KC  16            // K per smem stage
#define NSTEPS (H_/KC)    // 128
#define GRIDM (M_/TM)     // 32
#define GRIDN (V_/TN)     // 125
#define NTN 500           // 64-col LSE partial tiles (V/64)

#define SA  20            // smem row stride in floats (16 + 4 pad, conflict-free)
#define A_BYTES (128*SA*4)        // 10240
#define B_BYTES (256*SA*4)        // 20480
#define STAGE_BYTES (A_BYTES + B_BYTES)   // 30720
#define SM_BIAS (2*STAGE_BYTES)           // bias after the 2-stage ring
#define SMEM_TOTAL (SM_BIAS + 256*4)      // 62464

// ---------------- scratch (no allocations allowed) ----------------
__device__ int   g_is64;
__device__ float g_pmax[(size_t)M_ * NTN];
__device__ float g_psum[(size_t)M_ * NTN];
__device__ float g_tok [M_];
__device__ float g_losspt[M_];
__device__ float g_klpt  [M_];
__device__ float g_clippt[M_];
__device__ float g_maskpt[M_];

// ---------------- kernel 0: detect int32 vs int64 input_id ----------------
__global__ void detect_id64_kernel(const int* __restrict__ idw) {
    __shared__ int bad;
    if (threadIdx.x == 0) bad = 0;
    __syncthreads();
    int local = 0;
    for (int i = threadIdx.x; i < 2048; i += blockDim.x)
        if (idw[2 * i + 1] != 0) local = 1;
    if (local) atomicOr(&bad, 1);
    __syncthreads();
    if (threadIdx.x == 0) g_is64 = bad ? 0 : 1;
}

// ---------------- mma.sync tf32 helpers ----------------
__device__ __forceinline__ void mma_tf32(float* d, const uint32_t* a, const uint32_t* b) {
    asm volatile(
        "mma.sync.aligned.m16n8k8.row.col.f32.tf32.tf32.f32 "
        "{%0,%1,%2,%3}, {%4,%5,%6,%7}, {%8,%9}, {%0,%1,%2,%3};"
        : "+f"(d[0]), "+f"(d[1]), "+f"(d[2]), "+f"(d[3])
        : "r"(a[0]), "r"(a[1]), "r"(a[2]), "r"(a[3]), "r"(b[0]), "r"(b[1]));
}
__device__ __forceinline__ uint32_t f2tf(float f) {
    uint32_t r;
    asm("cvt.rna.tf32.f32 %0, %1;" : "=r"(r) : "f"(f));
    return r;
}
// split fp32 into tf32 hi + tf32 lo (3xTF32 decomposition)
__device__ __forceinline__ void split_tf32(float v, uint32_t& hi, uint32_t& lo) {
    hi = f2tf(v);
    lo = f2tf(v - __uint_as_float(hi));
}

// ---------------- kernel 1: 3xTF32 mma GEMM + streaming LSE ----------------
__global__ void __launch_bounds__(256, 1)
gemm_lse_mma(const float* __restrict__ X, const float* __restrict__ W,
             const float* __restrict__ bias, const void* __restrict__ idptr)
{
    extern __shared__ char smem[];
    float* sbias = (float*)(smem + SM_BIAS);

    const int tid = threadIdx.x, wid = tid >> 5, lid = tid & 31;
    const int g = lid >> 2, c = lid & 3;
    const int m0 = blockIdx.x * TM, n0 = blockIdx.y * TN;
    const int wm = (wid & 1) * 64;       // warp M offset (0/64)
    const int wn = (wid >> 1) * 64;      // warp N offset (0/64/128/192)

    sbias[tid] = bias[n0 + tid];

    // producer addressing: A = 512 float4 (128r x 4), B = 1024 float4 (256r x 4)
    const float4* gA[2]; const float4* gB[4];
    uint32_t sA[2], sB[4];
#pragma unroll
    for (int i = 0; i < 2; i++) {
        int idx = tid + 256 * i, r = idx >> 2, c4 = idx & 3;
        gA[i] = (const float4*)(X + (size_t)(m0 + r) * H_) + c4;
        sA[i] = (uint32_t)(r * SA + c4 * 4) * 4u;
    }
#pragma unroll
    for (int i = 0; i < 4; i++) {
        int idx = tid + 256 * i, r = idx >> 2, c4 = idx & 3;
        gB[i] = (const float4*)(W + (size_t)(n0 + r) * H_) + c4;
        sB[i] = (uint32_t)(A_BYTES) + (uint32_t)(r * SA + c4 * 4) * 4u;
    }

    float acc[4][8][4];
#pragma unroll
    for (int mf = 0; mf < 4; mf++)
#pragma unroll
        for (int nf = 0; nf < 8; nf++)
#pragma unroll
            for (int q = 0; q < 4; q++) acc[mf][nf][q] = 0.f;

    float4 ra[2], rb[4];
    // prologue: stage 0 -> smem, stage 1 -> regs
#pragma unroll
    for (int i = 0; i < 2; i++) ra[i] = gA[i][0];
#pragma unroll
    for (int i = 0; i < 4; i++) rb[i] = gB[i][0];
#pragma unroll
    for (int i = 0; i < 2; i++) *(float4*)(smem + sA[i]) = ra[i];
#pragma unroll
    for (int i = 0; i < 4; i++) *(float4*)(smem + sB[i]) = rb[i];
#pragma unroll
    for (int i = 0; i < 2; i++) ra[i] = gA[i][4];   // kt=1: +16 floats = +4 float4
#pragma unroll
    for (int i = 0; i < 4; i++) rb[i] = gB[i][4];
    __syncthreads();

    const float* As = (const float*)smem;
    const float* Bs = (const float*)(smem + A_BYTES);
    const uint32_t stageW = STAGE_BYTES / 4;   // stage stride in words

    for (int kt = 0; kt < NSTEPS; kt++) {
        const uint32_t cur = (uint32_t)(kt & 1) * stageW;
        // stage kt+1 regs -> smem buffer (kt+1)&1
        if (kt + 1 < NSTEPS) {
            char* dst = smem + (size_t)((kt + 1) & 1) * STAGE_BYTES;
#pragma unroll
            for (int i = 0; i < 2; i++) *(float4*)(dst + sA[i]) = ra[i];
#pragma unroll
            for (int i = 0; i < 4; i++) *(float4*)(dst + sB[i]) = rb[i];
        }
        if (kt + 2 < NSTEPS) {
            const int o = (kt + 2) * 4;
#pragma unroll
            for (int i = 0; i < 2; i++) ra[i] = gA[i][o];
#pragma unroll
            for (int i = 0; i < 4; i++) rb[i] = gB[i][o];
        }
        // compute current stage: 2 k-subs of 8, 3xTF32 per fragment pair
#pragma unroll
        for (int ks = 0; ks < 2; ks++) {
            const int k0 = ks * 8;
            uint32_t ah[4][4], al[4][4], bh[8][2], bl[8][2];
#pragma unroll
            for (int mf = 0; mf < 4; mf++) {
                const uint32_t r0 = cur + (uint32_t)((wm + mf * 16 + g) * SA + k0 + c);
                split_tf32(As[r0],            ah[mf][0], al[mf][0]);
                split_tf32(As[r0 + 8 * SA],   ah[mf][1], al[mf][1]);
                split_tf32(As[r0 + 4],        ah[mf][2], al[mf][2]);
                split_tf32(As[r0 + 8*SA + 4], ah[mf][3], al[mf][3]);
            }
#pragma unroll
            for (int nf = 0; nf < 8; nf++) {
                const uint32_t r0 = cur + (uint32_t)((wn + nf * 8 + g) * SA + k0 + c);
                split_tf32(Bs[r0],     bh[nf][0], bl[nf][0]);
                split_tf32(Bs[r0 + 4], bh[nf][1], bl[nf][1]);
            }
#pragma unroll
            for (int mf = 0; mf < 4; mf++)
#pragma unroll
                for (int nf = 0; nf < 8; nf++) {
                    mma_tf32(acc[mf][nf], al[mf], bh[nf]);  // xl*wh
                    mma_tf32(acc[mf][nf], ah[mf], bl[nf]);  // xh*wl
                    mma_tf32(acc[mf][nf], ah[mf], bh[nf]);  // xh*wh (largest last)
                }
        }
        __syncthreads();
    }

    // ---- epilogue: per-row bias + online (max, sumexp) over warp's 64 cols ----
    const bool is64 = (g_is64 != 0);
    const int tn = blockIdx.y * 4 + (wid >> 1);
#pragma unroll
    for (int mf = 0; mf < 4; mf++) {
#pragma unroll
        for (int rh = 0; rh < 2; rh++) {
            const int row = m0 + wm + mf * 16 + g + rh * 8;
            float vals[16];
            float mx = -CUDART_INF_F;
#pragma unroll
            for (int nf = 0; nf < 8; nf++)
#pragma unroll
                for (int b = 0; b < 2; b++) {
                    const float v = acc[mf][nf][rh * 2 + b] + sbias[wn + nf * 8 + 2 * c + b];
                    vals[nf * 2 + b] = v;
                    mx = fmaxf(mx, v);
                }
            // quad reduce (lanes differ only in c)
            mx = fmaxf(mx, __shfl_xor_sync(0xffffffffu, mx, 1));
            mx = fmaxf(mx, __shfl_xor_sync(0xffffffffu, mx, 2));
            float s = 0.f;
#pragma unroll
            for (int j = 0; j < 16; j++) s += __expf(vals[j] - mx);
            s += __shfl_xor_sync(0xffffffffu, s, 1);
            s += __shfl_xor_sync(0xffffffffu, s, 2);

            const int vid = is64 ? (int)((const long long*)idptr)[row]
                                 : ((const int*)idptr)[row];
            const int lc = vid - (n0 + wn);
            if (lc >= 0 && lc < 64) {
#pragma unroll
                for (int nf = 0; nf < 8; nf++)
#pragma unroll
                    for (int b = 0; b < 2; b++)
                        if (nf * 8 + 2 * c + b == lc) g_tok[row] = vals[nf * 2 + b];
            }
            if (c == 0) {
                g_pmax[(size_t)row * NTN + tn] = mx;
                g_psum[(size_t)row * NTN + tn] = s;
            }
        }
    }
}

// ---------------- kernel 2: combine partials, per-token GRPO terms ----------------
__global__ void combine_kernel(const int* __restrict__ amask,
                               const float* __restrict__ adv,
                               const float* __restrict__ ref,
                               const float* __restrict__ oldlp,
                               float* __restrict__ out)
{
    const int warp = threadIdx.x >> 5;
    const int lane = threadIdx.x & 31;
    const int t = blockIdx.x * 8 + warp;
    if (t >= M_) return;

    const float* pm = g_pmax + (size_t)t * NTN;
    const float* ps = g_psum + (size_t)t * NTN;
    float M = -CUDART_INF_F;
    for (int j = lane; j < NTN; j += 32) M = fmaxf(M, pm[j]);
#pragma unroll
    for (int o = 16; o; o >>= 1) M = fmaxf(M, __shfl_xor_sync(0xffffffffu, M, o));
    float S = 0.f;
    for (int j = lane; j < NTN; j += 32) S += ps[j] * expf(pm[j] - M);
#pragma unroll
    for (int o = 16; o; o >>= 1) S += __shfl_xor_sync(0xffffffffu, S, o);

    if (lane == 0) {
        const float lse  = M + logf(S);
        const float logp = g_tok[t] - lse;
        out[1 + t] = logp;

        const float mask = (float)amask[t];
        const float a    = adv[t / T_];
        const float d    = ref[t] - logp;
        const float kl   = expf(d) - d - 1.f;
        const float c1   = expf(logp - oldlp[t]);
        const float c2   = fminf(fmaxf(c1, 0.8f), 1.2f);
        const float l1   = c1 * a, l2 = c2 * a;
        const float ptl  = -(fminf(l1, l2) - 0.04f * kl);
        g_losspt[t] = ptl * mask;
        g_klpt  [t] = kl  * mask;
        g_clippt[t] = (l1 < l2 ? 1.f : 0.f) * mask;
        g_maskpt[t] = mask;
    }
}

// ---------------- kernel 3: deterministic final reductions ----------------
__global__ void finalize_kernel(float* __restrict__ out, int out_size)
{
    __shared__ float sl[1024], sk[1024], sc[1024], sm[1024];
    const int t = threadIdx.x;
    float l = 0.f, k = 0.f, c = 0.f, m = 0.f;
    for (int i = t; i < M_; i += 1024) {
        l += g_losspt[i]; k += g_klpt[i]; c += g_clippt[i]; m += g_maskpt[i];
    }
    sl[t] = l; sk[t] = k; sc[t] = c; sm[t] = m;
    __syncthreads();
    for (int s = 512; s; s >>= 1) {
        if (t < s) { sl[t]+=sl[t+s]; sk[t]+=sk[t+s]; sc[t]+=sc[t+s]; sm[t]+=sm[t+s]; }
        __syncthreads();
    }
    if (t == 0) {
        out[0]      = sl[0] / sm[0];
        out[M_ + 1] = sk[0] / sm[0];
        out[M_ + 2] = sc[0] / sm[0];
    }
    for (int i = M_ + 3 + t; i < out_size; i += 1024) out[i] = 0.f;
}

// ---------------- launch ----------------
extern "C" void kernel_launch(void* const* d_in, const int* in_sizes, int n_in,
                              void* d_out, int out_size)
{
    const float* x     = (const float*)d_in[0];
    const float* w     = (const float*)d_in[1];
    const float* bias  = (const float*)d_in[2];
    const void*  ids   = d_in[3];
    const int*   amask = (const int*)d_in[4];
    const float* adv   = (const float*)d_in[5];
    const float* ref   = (const float*)d_in[6];
    const float* oldlp = (const float*)d_in[7];
    float* out = (float*)d_out;

    cudaFuncSetAttribute(gemm_lse_mma, cudaFuncAttributeMaxDynamicSharedMemorySize,
                         (int)SMEM_TOTAL);

    detect_id64_kernel<<<1, 256>>>((const int*)ids);

    dim3 grid(GRIDM, GRIDN);    // x fast -> consecutive CTAs share W tile in L2
    gemm_lse_mma<<<grid, 256, SMEM_TOTAL>>>(x, w, bias, ids);

    combine_kernel<<<M_ / 8, 256>>>(amask, adv, ref, oldlp, out);
    finalize_kernel<<<1, 1024>>>(out, out_size);
}

// round 5
// speedup vs baseline: 2.3052x; 1.9679x over previous
#include <cuda_runtime.h>
#include <math_constants.h>
#include <cstdint>

// ---------------- problem constants ----------------
#define B_  4
#define T_  1024
#define M_  4096          // B*T tokens
#define H_  2048
#define V_  32000

// ---------------- GEMM tiling ----------------
#define TM  128           // CTA M tile
#define TN  256           // CTA N tile
#define KC  16            // K per smem stage
#define NSTEPS (H_/KC)    // 128
#define GRIDM (M_/TM)     // 32
#define GRIDN (V_/TN)     // 125
#define NTN 500           // 64-col LSE partial tiles (V/64)

#define SA  20            // smem row stride in floats (16 + 4 pad, conflict-free)
#define A_BYTES (128*SA*4)        // 10240
#define B_BYTES (256*SA*4)        // 20480
#define STAGE_BYTES (A_BYTES + B_BYTES)   // 30720
#define SM_BIAS (2*STAGE_BYTES)           // bias after the 2-stage ring
#define SMEM_TOTAL (SM_BIAS + 256*4)      // 62464

// ---------------- scratch (no allocations allowed) ----------------
__device__ int   g_is64;
__device__ float g_pmax[(size_t)M_ * NTN];
__device__ float g_psum[(size_t)M_ * NTN];
__device__ float g_tok [M_];
__device__ float g_losspt[M_];
__device__ float g_klpt  [M_];
__device__ float g_clippt[M_];
__device__ float g_maskpt[M_];

// ---------------- kernel 0: detect int32 vs int64 input_id ----------------
__global__ void detect_id64_kernel(const int* __restrict__ idw) {
    __shared__ int bad;
    if (threadIdx.x == 0) bad = 0;
    __syncthreads();
    int local = 0;
    for (int i = threadIdx.x; i < 2048; i += blockDim.x)
        if (idw[2 * i + 1] != 0) local = 1;
    if (local) atomicOr(&bad, 1);
    __syncthreads();
    if (threadIdx.x == 0) g_is64 = bad ? 0 : 1;
}

// ---------------- kernel 0b: exact fp32 target-token logits ----------------
// per_token_logps precision hinges on tok_logit; compute it exactly in fp32.
// One warp per token: gather W[vid], dot with X[t], add bias.
__global__ void tok_logit_kernel(const float* __restrict__ X,
                                 const float* __restrict__ W,
                                 const float* __restrict__ bias,
                                 const void* __restrict__ idptr)
{
    const int warp = threadIdx.x >> 5, lane = threadIdx.x & 31;
    const int t = blockIdx.x * 8 + warp;
    if (t >= M_) return;
    const int vid = g_is64 ? (int)((const long long*)idptr)[t]
                           : ((const int*)idptr)[t];
    const float4* xr = (const float4*)(X + (size_t)t * H_);
    const float4* wr = (const float4*)(W + (size_t)vid * H_);
    float s = 0.f;
#pragma unroll 4
    for (int i = lane; i < H_ / 4; i += 32) {
        float4 a = xr[i], b = wr[i];
        s += a.x * b.x + a.y * b.y + a.z * b.z + a.w * b.w;
    }
#pragma unroll
    for (int o = 16; o; o >>= 1) s += __shfl_xor_sync(0xffffffffu, s, o);
    if (lane == 0) g_tok[t] = s + bias[vid];
}

// ---------------- mma.sync tf32 helper ----------------
__device__ __forceinline__ void mma_tf32(float* d, const uint32_t* a, const uint32_t* b) {
    asm volatile(
        "mma.sync.aligned.m16n8k8.row.col.f32.tf32.tf32.f32 "
        "{%0,%1,%2,%3}, {%4,%5,%6,%7}, {%8,%9}, {%0,%1,%2,%3};"
        : "+f"(d[0]), "+f"(d[1]), "+f"(d[2]), "+f"(d[3])
        : "r"(a[0]), "r"(a[1]), "r"(a[2]), "r"(a[3]), "r"(b[0]), "r"(b[1]));
}

// ---------------- kernel 1: 1xTF32 mma GEMM + streaming LSE ----------------
// tf32 logit error is self-averaging inside logsumexp (dlse ~ 5e-6), so a
// single tf32 pass suffices here; the precision-critical token logit comes
// from tok_logit_kernel.
__global__ void __launch_bounds__(256, 1)
gemm_lse_mma(const float* __restrict__ X, const float* __restrict__ W,
             const float* __restrict__ bias)
{
    extern __shared__ char smem[];
    float* sbias = (float*)(smem + SM_BIAS);

    const int tid = threadIdx.x, wid = tid >> 5, lid = tid & 31;
    const int g = lid >> 2, c = lid & 3;
    const int m0 = blockIdx.x * TM, n0 = blockIdx.y * TN;
    const int wm = (wid & 1) * 64;       // warp M offset (0/64)
    const int wn = (wid >> 1) * 64;      // warp N offset (0/64/128/192)

    sbias[tid] = bias[n0 + tid];

    // producer addressing: A = 512 float4 (128r x 4), B = 1024 float4 (256r x 4)
    const float4* gA[2]; const float4* gB[4];
    uint32_t sA[2], sB[4];
#pragma unroll
    for (int i = 0; i < 2; i++) {
        int idx = tid + 256 * i, r = idx >> 2, c4 = idx & 3;
        gA[i] = (const float4*)(X + (size_t)(m0 + r) * H_) + c4;
        sA[i] = (uint32_t)(r * SA + c4 * 4) * 4u;
    }
#pragma unroll
    for (int i = 0; i < 4; i++) {
        int idx = tid + 256 * i, r = idx >> 2, c4 = idx & 3;
        gB[i] = (const float4*)(W + (size_t)(n0 + r) * H_) + c4;
        sB[i] = (uint32_t)(A_BYTES) + (uint32_t)(r * SA + c4 * 4) * 4u;
    }

    float acc[4][8][4];
#pragma unroll
    for (int mf = 0; mf < 4; mf++)
#pragma unroll
        for (int nf = 0; nf < 8; nf++)
#pragma unroll
            for (int q = 0; q < 4; q++) acc[mf][nf][q] = 0.f;

    float4 ra[2], rb[4];
    // prologue: stage 0 -> smem, stage 1 -> regs
#pragma unroll
    for (int i = 0; i < 2; i++) ra[i] = gA[i][0];
#pragma unroll
    for (int i = 0; i < 4; i++) rb[i] = gB[i][0];
#pragma unroll
    for (int i = 0; i < 2; i++) *(float4*)(smem + sA[i]) = ra[i];
#pragma unroll
    for (int i = 0; i < 4; i++) *(float4*)(smem + sB[i]) = rb[i];
#pragma unroll
    for (int i = 0; i < 2; i++) ra[i] = gA[i][4];   // kt=1: +16 floats = +4 float4
#pragma unroll
    for (int i = 0; i < 4; i++) rb[i] = gB[i][4];
    __syncthreads();

    const uint32_t* As = (const uint32_t*)smem;
    const uint32_t* Bs = (const uint32_t*)(smem + A_BYTES);
    const uint32_t stageW = STAGE_BYTES / 4;   // stage stride in words

    for (int kt = 0; kt < NSTEPS; kt++) {
        const uint32_t cur = (uint32_t)(kt & 1) * stageW;
        // stage kt+1 regs -> smem buffer (kt+1)&1
        if (kt + 1 < NSTEPS) {
            char* dst = smem + (size_t)((kt + 1) & 1) * STAGE_BYTES;
#pragma unroll
            for (int i = 0; i < 2; i++) *(float4*)(dst + sA[i]) = ra[i];
#pragma unroll
            for (int i = 0; i < 4; i++) *(float4*)(dst + sB[i]) = rb[i];
        }
        if (kt + 2 < NSTEPS) {
            const int o = (kt + 2) * 4;
#pragma unroll
            for (int i = 0; i < 2; i++) ra[i] = gA[i][o];
#pragma unroll
            for (int i = 0; i < 4; i++) rb[i] = gB[i][o];
        }
        // compute current stage: 2 k-subs of 8
#pragma unroll
        for (int ks = 0; ks < 2; ks++) {
            const int k0 = ks * 8;
            uint32_t af[4][4], bf[8][2];
#pragma unroll
            for (int mf = 0; mf < 4; mf++) {
                const uint32_t r0 = cur + (uint32_t)((wm + mf * 16 + g) * SA + k0 + c);
                af[mf][0] = As[r0];
                af[mf][1] = As[r0 + 8 * SA];
                af[mf][2] = As[r0 + 4];
                af[mf][3] = As[r0 + 8 * SA + 4];
            }
#pragma unroll
            for (int nf = 0; nf < 8; nf++) {
                const uint32_t r0 = cur + (uint32_t)((wn + nf * 8 + g) * SA + k0 + c);
                bf[nf][0] = Bs[r0];
                bf[nf][1] = Bs[r0 + 4];
            }
#pragma unroll
            for (int mf = 0; mf < 4; mf++)
#pragma unroll
                for (int nf = 0; nf < 8; nf++)
                    mma_tf32(acc[mf][nf], af[mf], bf[nf]);
        }
        __syncthreads();
    }

    // ---- epilogue: per-row bias + online (max, sumexp) over warp's 64 cols ----
    const int tn = blockIdx.y * 4 + (wid >> 1);
#pragma unroll
    for (int mf = 0; mf < 4; mf++) {
#pragma unroll
        for (int rh = 0; rh < 2; rh++) {
            const int row = m0 + wm + mf * 16 + g + rh * 8;
            float vals[16];
            float mx = -CUDART_INF_F;
#pragma unroll
            for (int nf = 0; nf < 8; nf++)
#pragma unroll
                for (int b = 0; b < 2; b++) {
                    const float v = acc[mf][nf][rh * 2 + b] + sbias[wn + nf * 8 + 2 * c + b];
                    vals[nf * 2 + b] = v;
                    mx = fmaxf(mx, v);
                }
            // quad reduce (lanes differ only in c)
            mx = fmaxf(mx, __shfl_xor_sync(0xffffffffu, mx, 1));
            mx = fmaxf(mx, __shfl_xor_sync(0xffffffffu, mx, 2));
            float s = 0.f;
#pragma unroll
            for (int j = 0; j < 16; j++) s += __expf(vals[j] - mx);
            s += __shfl_xor_sync(0xffffffffu, s, 1);
            s += __shfl_xor_sync(0xffffffffu, s, 2);

            if (c == 0) {
                g_pmax[(size_t)row * NTN + tn] = mx;
                g_psum[(size_t)row * NTN + tn] = s;
            }
        }
    }
}

// ---------------- kernel 2: combine partials, per-token GRPO terms ----------------
__global__ void combine_kernel(const int* __restrict__ amask,
                               const float* __restrict__ adv,
                               const float* __restrict__ ref,
                               const float* __restrict__ oldlp,
                               float* __restrict__ out)
{
    const int warp = threadIdx.x >> 5;
    const int lane = threadIdx.x & 31;
    const int t = blockIdx.x * 8 + warp;
    if (t >= M_) return;

    const float* pm = g_pmax + (size_t)t * NTN;
    const float* ps = g_psum + (size_t)t * NTN;
    float M = -CUDART_INF_F;
    for (int j = lane; j < NTN; j += 32) M = fmaxf(M, pm[j]);
#pragma unroll
    for (int o = 16; o; o >>= 1) M = fmaxf(M, __shfl_xor_sync(0xffffffffu, M, o));
    float S = 0.f;
    for (int j = lane; j < NTN; j += 32) S += ps[j] * expf(pm[j] - M);
#pragma unroll
    for (int o = 16; o; o >>= 1) S += __shfl_xor_sync(0xffffffffu, S, o);

    if (lane == 0) {
        const float lse  = M + logf(S);
        const float logp = g_tok[t] - lse;
        out[1 + t] = logp;

        const float mask = (float)amask[t];
        const float a    = adv[t / T_];
        const float d    = ref[t] - logp;
        const float kl   = expf(d) - d - 1.f;
        const float c1   = expf(logp - oldlp[t]);
        const float c2   = fminf(fmaxf(c1, 0.8f), 1.2f);
        const float l1   = c1 * a, l2 = c2 * a;
        const float ptl  = -(fminf(l1, l2) - 0.04f * kl);
        g_losspt[t] = ptl * mask;
        g_klpt  [t] = kl  * mask;
        g_clippt[t] = (l1 < l2 ? 1.f : 0.f) * mask;
        g_maskpt[t] = mask;
    }
}

// ---------------- kernel 3: deterministic final reductions ----------------
__global__ void finalize_kernel(float* __restrict__ out, int out_size)
{
    __shared__ float sl[1024], sk[1024], sc[1024], sm[1024];
    const int t = threadIdx.x;
    float l = 0.f, k = 0.f, c = 0.f, m = 0.f;
    for (int i = t; i < M_; i += 1024) {
        l += g_losspt[i]; k += g_klpt[i]; c += g_clippt[i]; m += g_maskpt[i];
    }
    sl[t] = l; sk[t] = k; sc[t] = c; sm[t] = m;
    __syncthreads();
    for (int s = 512; s; s >>= 1) {
        if (t < s) { sl[t]+=sl[t+s]; sk[t]+=sk[t+s]; sc[t]+=sc[t+s]; sm[t]+=sm[t+s]; }
        __syncthreads();
    }
    if (t == 0) {
        out[0]      = sl[0] / sm[0];
        out[M_ + 1] = sk[0] / sm[0];
        out[M_ + 2] = sc[0] / sm[0];
    }
    for (int i = M_ + 3 + t; i < out_size; i += 1024) out[i] = 0.f;
}

// ---------------- launch ----------------
extern "C" void kernel_launch(void* const* d_in, const int* in_sizes, int n_in,
                              void* d_out, int out_size)
{
    const float* x     = (const float*)d_in[0];
    const float* w     = (const float*)d_in[1];
    const float* bias  = (const float*)d_in[2];
    const void*  ids   = d_in[3];
    const int*   amask = (const int*)d_in[4];
    const float* adv   = (const float*)d_in[5];
    const float* ref   = (const float*)d_in[6];
    const float* oldlp = (const float*)d_in[7];
    float* out = (float*)d_out;

    cudaFuncSetAttribute(gemm_lse_mma, cudaFuncAttributeMaxDynamicSharedMemorySize,
                         (int)SMEM_TOTAL);

    detect_id64_kernel<<<1, 256>>>((const int*)ids);
    tok_logit_kernel<<<M_ / 8, 256>>>(x, w, bias, ids);

    dim3 grid(GRIDM, GRIDN);    // x fast -> consecutive CTAs share W tile in L2
    gemm_lse_mma<<<grid, 256, SMEM_TOTAL>>>(x, w, bias);

    combine_kernel<<<M_ / 8, 256>>>(amask, adv, ref, oldlp, out);
    finalize_kernel<<<1, 1024>>>(out, out_size);
}

// round 6
// speedup vs baseline: 2.4873x; 1.0790x over previous
#include <cuda_runtime.h>
#include <math_constants.h>
#include <cstdint>

// ---------------- problem constants ----------------
#define B_  4
#define T_  1024
#define M_  4096          // B*T tokens
#define H_  2048
#define V_  32000

// ---------------- GEMM tiling ----------------
#define TM  128           // CTA M tile
#define TN  256           // CTA N tile
#define KC  16            // K per smem stage
#define NSTEPS (H_/KC)    // 128
#define NSTAGE 3
#define GRIDM (M_/TM)     // 32
#define GRIDN (V_/TN)     // 125
#define NTN 1000          // 32-col LSE partial tiles (V/32)

#define SA  20            // smem row stride in floats (16 + 4 pad, conflict-free)
#define A_BYTES (128*SA*4)        // 10240
#define B_BYTES (256*SA*4)        // 20480
#define STAGE_BYTES (A_BYTES + B_BYTES)   // 30720
#define STAGE_WORDS (STAGE_BYTES/4)
#define SM_BIAS (NSTAGE*STAGE_BYTES)      // bias after the 3-stage ring
#define SMEM_TOTAL (SM_BIAS + 256*4)      // 93184

// ---------------- scratch (no allocations allowed) ----------------
__device__ int   g_is64;
__device__ float g_pmax[(size_t)M_ * NTN];
__device__ float g_psum[(size_t)M_ * NTN];
__device__ float g_tok [M_];
__device__ float g_losspt[M_];
__device__ float g_klpt  [M_];
__device__ float g_clippt[M_];
__device__ float g_maskpt[M_];

// ---------------- kernel 0: detect int32 vs int64 input_id ----------------
__global__ void detect_id64_kernel(const int* __restrict__ idw) {
    __shared__ int bad;
    if (threadIdx.x == 0) bad = 0;
    __syncthreads();
    int local = 0;
    for (int i = threadIdx.x; i < 2048; i += blockDim.x)
        if (idw[2 * i + 1] != 0) local = 1;
    if (local) atomicOr(&bad, 1);
    __syncthreads();
    if (threadIdx.x == 0) g_is64 = bad ? 0 : 1;
}

// ---------------- kernel 0b: exact fp32 target-token logits ----------------
__global__ void tok_logit_kernel(const float* __restrict__ X,
                                 const float* __restrict__ W,
                                 const float* __restrict__ bias,
                                 const void* __restrict__ idptr)
{
    const int warp = threadIdx.x >> 5, lane = threadIdx.x & 31;
    const int t = blockIdx.x * 8 + warp;
    if (t >= M_) return;
    const int vid = g_is64 ? (int)((const long long*)idptr)[t]
                           : ((const int*)idptr)[t];
    const float4* xr = (const float4*)(X + (size_t)t * H_);
    const float4* wr = (const float4*)(W + (size_t)vid * H_);
    float s = 0.f;
#pragma unroll 4
    for (int i = lane; i < H_ / 4; i += 32) {
        float4 a = xr[i], b = wr[i];
        s += a.x * b.x + a.y * b.y + a.z * b.z + a.w * b.w;
    }
#pragma unroll
    for (int o = 16; o; o >>= 1) s += __shfl_xor_sync(0xffffffffu, s, o);
    if (lane == 0) g_tok[t] = s + bias[vid];
}

// ---------------- ptx helpers ----------------
__device__ __forceinline__ void mma_tf32(float* d, const uint32_t* a, const uint32_t* b) {
    asm volatile(
        "mma.sync.aligned.m16n8k8.row.col.f32.tf32.tf32.f32 "
        "{%0,%1,%2,%3}, {%4,%5,%6,%7}, {%8,%9}, {%0,%1,%2,%3};"
        : "+f"(d[0]), "+f"(d[1]), "+f"(d[2]), "+f"(d[3])
        : "r"(a[0]), "r"(a[1]), "r"(a[2]), "r"(a[3]), "r"(b[0]), "r"(b[1]));
}
__device__ __forceinline__ uint32_t cvta_smem(const void* p) {
    uint32_t a;
    asm("{ .reg .u64 t; cvta.to.shared.u64 t, %1; cvt.u32.u64 %0, t; }" : "=r"(a) : "l"(p));
    return a;
}
__device__ __forceinline__ void cp16(uint32_t dst, const void* src) {
    asm volatile("cp.async.cg.shared.global [%0], [%1], 16;" :: "r"(dst), "l"(src));
}
__device__ __forceinline__ void cp_commit() {
    asm volatile("cp.async.commit_group;" ::: "memory");
}
__device__ __forceinline__ void cp_wait1() {
    asm volatile("cp.async.wait_group 1;" ::: "memory");
}

// ---------------- kernel 1: 1xTF32 mma GEMM + streaming LSE ----------------
// 512 threads (16 warps, warp tile 64x32), 3-stage cp.async pipeline.
// Per-output k-accumulation order identical to previous round (bitwise-stable).
__global__ void __launch_bounds__(512, 1)
gemm_lse_mma(const float* __restrict__ X, const float* __restrict__ W,
             const float* __restrict__ bias)
{
    extern __shared__ char smem[];
    float* sbias = (float*)(smem + SM_BIAS);
    const uint32_t sb = cvta_smem(smem);

    const int tid = threadIdx.x, wid = tid >> 5, lid = tid & 31;
    const int g = lid >> 2, c = lid & 3;
    const int m0 = blockIdx.x * TM, n0 = blockIdx.y * TN;
    const int wm = (wid & 1) * 64;       // warp M offset (0/64)
    const int wni = wid >> 1;            // 0..7
    const int wn = wni * 32;             // warp N offset

    if (tid < 256) sbias[tid] = bias[n0 + tid];

    // producer addressing (cp.async 16B each):
    // A: 128 rows x 4 f4 = 512 -> 1/thread ; B: 256 rows x 4 f4 = 1024 -> 2/thread
    const float4* gA0;  uint32_t dA0;
    const float4* gB0[2]; uint32_t dB0[2];
    {
        int r = tid >> 2, c4 = tid & 3;
        gA0 = (const float4*)(X + (size_t)(m0 + r) * H_) + c4;
        dA0 = (uint32_t)(r * SA + c4 * 4) * 4u;
    }
#pragma unroll
    for (int i = 0; i < 2; i++) {
        int idx = tid + 512 * i, r = idx >> 2, c4 = idx & 3;
        gB0[i] = (const float4*)(W + (size_t)(n0 + r) * H_) + c4;
        dB0[i] = (uint32_t)A_BYTES + (uint32_t)(r * SA + c4 * 4) * 4u;
    }

    float acc[4][4][4];
#pragma unroll
    for (int mf = 0; mf < 4; mf++)
#pragma unroll
        for (int nf = 0; nf < 4; nf++)
#pragma unroll
            for (int q = 0; q < 4; q++) acc[mf][nf][q] = 0.f;

    // prologue: fill stages 0 and 1
#pragma unroll
    for (int s = 0; s < 2; s++) {
        const uint32_t stb = sb + (uint32_t)s * STAGE_BYTES;
        cp16(stb + dA0, gA0 + s * 4);
        cp16(stb + dB0[0], gB0[0] + s * 4);
        cp16(stb + dB0[1], gB0[1] + s * 4);
        cp_commit();
    }

    const uint32_t* Sw = (const uint32_t*)smem;
    int slot = 0, fslot = 2;

    for (int kt = 0; kt < NSTEPS; kt++) {
        cp_wait1();
        __syncthreads();       // stage `slot` visible to all; slot `fslot` free

        // issue fill for kt+2 into fslot
        if (kt + 2 < NSTEPS) {
            const uint32_t stb = sb + (uint32_t)fslot * STAGE_BYTES;
            const int o = (kt + 2) * 4;
            cp16(stb + dA0, gA0 + o);
            cp16(stb + dB0[0], gB0[0] + o);
            cp16(stb + dB0[1], gB0[1] + o);
        }
        cp_commit();

        const uint32_t cur = (uint32_t)slot * STAGE_WORDS;
        const uint32_t bbase = cur + (A_BYTES / 4);
#pragma unroll
        for (int ks = 0; ks < 2; ks++) {
            const int k0 = ks * 8;
            uint32_t af[4][4], bf[4][2];
#pragma unroll
            for (int mf = 0; mf < 4; mf++) {
                const uint32_t r0 = cur + (uint32_t)((wm + mf * 16 + g) * SA + k0 + c);
                af[mf][0] = Sw[r0];
                af[mf][1] = Sw[r0 + 8 * SA];
                af[mf][2] = Sw[r0 + 4];
                af[mf][3] = Sw[r0 + 8 * SA + 4];
            }
#pragma unroll
            for (int nf = 0; nf < 4; nf++) {
                const uint32_t r0 = bbase + (uint32_t)((wn + nf * 8 + g) * SA + k0 + c);
                bf[nf][0] = Sw[r0];
                bf[nf][1] = Sw[r0 + 4];
            }
#pragma unroll
            for (int mf = 0; mf < 4; mf++)
#pragma unroll
                for (int nf = 0; nf < 4; nf++)
                    mma_tf32(acc[mf][nf], af[mf], bf[nf]);
        }
        __syncthreads();       // all reads of `slot` done before it is refilled
        if (++slot == NSTAGE) slot = 0;
        if (++fslot == NSTAGE) fslot = 0;
    }

    // ---- epilogue: per-row bias + (max, sumexp) over warp's 32 cols ----
    const int tn = blockIdx.y * 8 + wni;
#pragma unroll
    for (int mf = 0; mf < 4; mf++) {
#pragma unroll
        for (int rh = 0; rh < 2; rh++) {
            const int row = m0 + wm + mf * 16 + g + rh * 8;
            float vals[8];
            float mx = -CUDART_INF_F;
#pragma unroll
            for (int nf = 0; nf < 4; nf++)
#pragma unroll
                for (int b = 0; b < 2; b++) {
                    const float v = acc[mf][nf][rh * 2 + b] + sbias[wn + nf * 8 + 2 * c + b];
                    vals[nf * 2 + b] = v;
                    mx = fmaxf(mx, v);
                }
            mx = fmaxf(mx, __shfl_xor_sync(0xffffffffu, mx, 1));
            mx = fmaxf(mx, __shfl_xor_sync(0xffffffffu, mx, 2));
            float s = 0.f;
#pragma unroll
            for (int j = 0; j < 8; j++) s += __expf(vals[j] - mx);
            s += __shfl_xor_sync(0xffffffffu, s, 1);
            s += __shfl_xor_sync(0xffffffffu, s, 2);
            if (c == 0) {
                g_pmax[(size_t)row * NTN + tn] = mx;
                g_psum[(size_t)row * NTN + tn] = s;
            }
        }
    }
}

// ---------------- kernel 2: combine partials, per-token GRPO terms ----------------
__global__ void combine_kernel(const int* __restrict__ amask,
                               const float* __restrict__ adv,
                               const float* __restrict__ ref,
                               const float* __restrict__ oldlp,
                               float* __restrict__ out)
{
    const int warp = threadIdx.x >> 5;
    const int lane = threadIdx.x & 31;
    const int t = blockIdx.x * 8 + warp;
    if (t >= M_) return;

    const float* pm = g_pmax + (size_t)t * NTN;
    const float* ps = g_psum + (size_t)t * NTN;
    float M = -CUDART_INF_F;
    for (int j = lane; j < NTN; j += 32) M = fmaxf(M, pm[j]);
#pragma unroll
    for (int o = 16; o; o >>= 1) M = fmaxf(M, __shfl_xor_sync(0xffffffffu, M, o));
    float S = 0.f;
    for (int j = lane; j < NTN; j += 32) S += ps[j] * expf(pm[j] - M);
#pragma unroll
    for (int o = 16; o; o >>= 1) S += __shfl_xor_sync(0xffffffffu, S, o);

    if (lane == 0) {
        const float lse  = M + logf(S);
        const float logp = g_tok[t] - lse;
        out[1 + t] = logp;

        const float mask = (float)amask[t];
        const float a    = adv[t / T_];
        const float d    = ref[t] - logp;
        const float kl   = expf(d) - d - 1.f;
        const float c1   = expf(logp - oldlp[t]);
        const float c2   = fminf(fmaxf(c1, 0.8f), 1.2f);
        const float l1   = c1 * a, l2 = c2 * a;
        const float ptl  = -(fminf(l1, l2) - 0.04f * kl);
        g_losspt[t] = ptl * mask;
        g_klpt  [t] = kl  * mask;
        g_clippt[t] = (l1 < l2 ? 1.f : 0.f) * mask;
        g_maskpt[t] = mask;
    }
}

// ---------------- kernel 3: deterministic final reductions ----------------
__global__ void finalize_kernel(float* __restrict__ out, int out_size)
{
    __shared__ float sl[1024], sk[1024], sc[1024], sm[1024];
    const int t = threadIdx.x;
    float l = 0.f, k = 0.f, c = 0.f, m = 0.f;
    for (int i = t; i < M_; i += 1024) {
        l += g_losspt[i]; k += g_klpt[i]; c += g_clippt[i]; m += g_maskpt[i];
    }
    sl[t] = l; sk[t] = k; sc[t] = c; sm[t] = m;
    __syncthreads();
    for (int s = 512; s; s >>= 1) {
        if (t < s) { sl[t]+=sl[t+s]; sk[t]+=sk[t+s]; sc[t]+=sc[t+s]; sm[t]+=sm[t+s]; }
        __syncthreads();
    }
    if (t == 0) {
        out[0]      = sl[0] / sm[0];
        out[M_ + 1] = sk[0] / sm[0];
        out[M_ + 2] = sc[0] / sm[0];
    }
    for (int i = M_ + 3 + t; i < out_size; i += 1024) out[i] = 0.f;
}

// ---------------- launch ----------------
extern "C" void kernel_launch(void* const* d_in, const int* in_sizes, int n_in,
                              void* d_out, int out_size)
{
    const float* x     = (const float*)d_in[0];
    const float* w     = (const float*)d_in[1];
    const float* bias  = (const float*)d_in[2];
    const void*  ids   = d_in[3];
    const int*   amask = (const int*)d_in[4];
    const float* adv   = (const float*)d_in[5];
    const float* ref   = (const float*)d_in[6];
    const float* oldlp = (const float*)d_in[7];
    float* out = (float*)d_out;

    cudaFuncSetAttribute(gemm_lse_mma, cudaFuncAttributeMaxDynamicSharedMemorySize,
                         (int)SMEM_TOTAL);

    detect_id64_kernel<<<1, 256>>>((const int*)ids);
    tok_logit_kernel<<<M_ / 8, 256>>>(x, w, bias, ids);

    dim3 grid(GRIDM, GRIDN);    // x fast -> consecutive CTAs share W tile in L2
    gemm_lse_mma<<<grid, 512, SMEM_TOTAL>>>(x, w, bias);

    combine_kernel<<<M_ / 8, 256>>>(amask, adv, ref, oldlp, out);
    finalize_kernel<<<1, 1024>>>(out, out_size);
}

// round 7
// speedup vs baseline: 4.6951x; 1.8876x over previous
#include <cuda_runtime.h>
#include <cuda_fp16.h>
#include <math_constants.h>
#include <cstdint>

// ---------------- problem constants ----------------
#define B_  4
#define T_  1024
#define M_  4096          // B*T tokens
#define H_  2048
#define V_  32000

// ---------------- GEMM tiling ----------------
#define TM  128           // CTA M tile
#define TN  256           // CTA N tile
#define KCH 32            // K elements (halfs) per smem stage
#define NSTEPS (H_/KCH)   // 64
#define NSTAGE 3
#define GRIDM (M_/TM)     // 32
#define GRIDN (V_/TN)     // 125
#define NTN 1000          // 32-col LSE partial tiles (V/32)

#define SA  20            // smem row stride in 32-bit words (16 data + 4 pad)
#define A_BYTES (128*SA*4)        // 10240
#define B_BYTES (256*SA*4)        // 20480
#define STAGE_BYTES (A_BYTES + B_BYTES)   // 30720
#define STAGE_WORDS (STAGE_BYTES/4)
#define SM_BIAS (NSTAGE*STAGE_BYTES)      // bias after the 3-stage ring
#define SMEM_TOTAL (SM_BIAS + 256*4)      // 93184

// ---------------- scratch (no allocations allowed) ----------------
__device__ int    g_is64;
__device__ __half g_Wh[(size_t)V_ * H_];   // fp16 weight copy (131 MB)
__device__ __half g_Xh[(size_t)M_ * H_];   // fp16 activation copy (16 MB)
__device__ float  g_pmax[(size_t)M_ * NTN];
__device__ float  g_psum[(size_t)M_ * NTN];
__device__ float  g_tok [M_];
__device__ float  g_losspt[M_];
__device__ float  g_klpt  [M_];
__device__ float  g_clippt[M_];
__device__ float  g_maskpt[M_];

// ---------------- kernel 0: detect int32 vs int64 input_id ----------------
__global__ void detect_id64_kernel(const int* __restrict__ idw) {
    __shared__ int bad;
    if (threadIdx.x == 0) bad = 0;
    __syncthreads();
    int local = 0;
    for (int i = threadIdx.x; i < 2048; i += blockDim.x)
        if (idw[2 * i + 1] != 0) local = 1;
    if (local) atomicOr(&bad, 1);
    __syncthreads();
    if (threadIdx.x == 0) g_is64 = bad ? 0 : 1;
}

// ---------------- kernel 0a: fp32 -> fp16 conversion (8 elems/thread) ----------------
__global__ void convert_half_kernel(const float* __restrict__ src,
                                    __half* __restrict__ dst, int n8)
{
    const int i = blockIdx.x * blockDim.x + threadIdx.x;
    if (i >= n8) return;
    const float4* s = (const float4*)src + 2 * i;
    float4 a = s[0], b = s[1];
    __half2 h[4];
    h[0] = __floats2half2_rn(a.x, a.y);
    h[1] = __floats2half2_rn(a.z, a.w);
    h[2] = __floats2half2_rn(b.x, b.y);
    h[3] = __floats2half2_rn(b.z, b.w);
    *(uint4*)((__half2*)dst + 4 * (size_t)i) = *(uint4*)h;
}

// ---------------- kernel 0b: exact fp32 target-token logits ----------------
__global__ void tok_logit_kernel(const float* __restrict__ X,
                                 const float* __restrict__ W,
                                 const float* __restrict__ bias,
                                 const void* __restrict__ idptr)
{
    const int warp = threadIdx.x >> 5, lane = threadIdx.x & 31;
    const int t = blockIdx.x * 8 + warp;
    if (t >= M_) return;
    const int vid = g_is64 ? (int)((const long long*)idptr)[t]
                           : ((const int*)idptr)[t];
    const float4* xr = (const float4*)(X + (size_t)t * H_);
    const float4* wr = (const float4*)(W + (size_t)vid * H_);
    float s = 0.f;
#pragma unroll 4
    for (int i = lane; i < H_ / 4; i += 32) {
        float4 a = xr[i], b = wr[i];
        s += a.x * b.x + a.y * b.y + a.z * b.z + a.w * b.w;
    }
#pragma unroll
    for (int o = 16; o; o >>= 1) s += __shfl_xor_sync(0xffffffffu, s, o);
    if (lane == 0) g_tok[t] = s + bias[vid];
}

// ---------------- ptx helpers ----------------
__device__ __forceinline__ void mma_f16(float* d, const uint32_t* a, const uint32_t* b) {
    asm volatile(
        "mma.sync.aligned.m16n8k16.row.col.f32.f16.f16.f32 "
        "{%0,%1,%2,%3}, {%4,%5,%6,%7}, {%8,%9}, {%0,%1,%2,%3};"
        : "+f"(d[0]), "+f"(d[1]), "+f"(d[2]), "+f"(d[3])
        : "r"(a[0]), "r"(a[1]), "r"(a[2]), "r"(a[3]), "r"(b[0]), "r"(b[1]));
}
__device__ __forceinline__ uint32_t cvta_smem(const void* p) {
    uint32_t a;
    asm("{ .reg .u64 t; cvta.to.shared.u64 t, %1; cvt.u32.u64 %0, t; }" : "=r"(a) : "l"(p));
    return a;
}
__device__ __forceinline__ void cp16(uint32_t dst, const void* src) {
    asm volatile("cp.async.cg.shared.global [%0], [%1], 16;" :: "r"(dst), "l"(src));
}
__device__ __forceinline__ void cp_commit() {
    asm volatile("cp.async.commit_group;" ::: "memory");
}
__device__ __forceinline__ void cp_wait1() {
    asm volatile("cp.async.wait_group 1;" ::: "memory");
}

// ---------------- kernel 1: fp16 mma GEMM + streaming LSE ----------------
// 512 threads (16 warps, warp tile 64x32), 3-stage cp.async pipeline.
// fp16 has the same 11-bit mantissa as tf32: identical logit noise, half the
// HMMA instruction count (k16 vs k8). K-accumulation ascending (deterministic).
__global__ void __launch_bounds__(512, 1)
gemm_lse_mma(const float* __restrict__ bias)
{
    extern __shared__ char smem[];
    float* sbias = (float*)(smem + SM_BIAS);
    const uint32_t sb = cvta_smem(smem);

    const int tid = threadIdx.x, wid = tid >> 5, lid = tid & 31;
    const int g = lid >> 2, c = lid & 3;
    const int m0 = blockIdx.x * TM, n0 = blockIdx.y * TN;
    const int wm = (wid & 1) * 64;       // warp M offset (0/64)
    const int wni = wid >> 1;            // 0..7
    const int wn = wni * 32;             // warp N offset

    if (tid < 256) sbias[tid] = bias[n0 + tid];

    // producer addressing (cp.async 16B = 8 halfs each):
    // A: 128 rows x 4 chunks = 512 -> 1/thread ; B: 256 rows x 4 = 1024 -> 2/thread
    const __half* gA0;  uint32_t dA0;
    const __half* gB0[2]; uint32_t dB0[2];
    {
        int r = tid >> 2, c4 = tid & 3;
        gA0 = g_Xh + (size_t)(m0 + r) * H_ + c4 * 8;
        dA0 = (uint32_t)(r * SA + c4 * 4) * 4u;
    }
#pragma unroll
    for (int i = 0; i < 2; i++) {
        int idx = tid + 512 * i, r = idx >> 2, c4 = idx & 3;
        gB0[i] = g_Wh + (size_t)(n0 + r) * H_ + c4 * 8;
        dB0[i] = (uint32_t)A_BYTES + (uint32_t)(r * SA + c4 * 4) * 4u;
    }

    float acc[4][4][4];
#pragma unroll
    for (int mf = 0; mf < 4; mf++)
#pragma unroll
        for (int nf = 0; nf < 4; nf++)
#pragma unroll
            for (int q = 0; q < 4; q++) acc[mf][nf][q] = 0.f;

    // prologue: fill stages 0 and 1
#pragma unroll
    for (int s = 0; s < 2; s++) {
        const uint32_t stb = sb + (uint32_t)s * STAGE_BYTES;
        cp16(stb + dA0, gA0 + s * KCH);
        cp16(stb + dB0[0], gB0[0] + s * KCH);
        cp16(stb + dB0[1], gB0[1] + s * KCH);
        cp_commit();
    }

    const uint32_t* Sw = (const uint32_t*)smem;
    int slot = 0, fslot = 2;

    for (int kt = 0; kt < NSTEPS; kt++) {
        cp_wait1();
        __syncthreads();       // stage `slot` visible; slot `fslot` free

        if (kt + 2 < NSTEPS) {
            const uint32_t stb = sb + (uint32_t)fslot * STAGE_BYTES;
            const int o = (kt + 2) * KCH;
            cp16(stb + dA0, gA0 + o);
            cp16(stb + dB0[0], gB0[0] + o);
            cp16(stb + dB0[1], gB0[1] + o);
        }
        cp_commit();

        const uint32_t cur = (uint32_t)slot * STAGE_WORDS;
        const uint32_t bbase = cur + (A_BYTES / 4);
        // 2 k16 sub-steps per stage (words 0..7 and 8..15)
#pragma unroll
        for (int ks = 0; ks < 2; ks++) {
            const int k0 = ks * 8;
            uint32_t af[4][4], bf[4][2];
#pragma unroll
            for (int mf = 0; mf < 4; mf++) {
                const uint32_t r0 = cur + (uint32_t)((wm + mf * 16 + g) * SA + k0 + c);
                af[mf][0] = Sw[r0];            // row g,   k halfs 2c..2c+1
                af[mf][1] = Sw[r0 + 8 * SA];   // row g+8
                af[mf][2] = Sw[r0 + 4];        // row g,   k halfs 2c+8..9
                af[mf][3] = Sw[r0 + 8 * SA + 4];
            }
#pragma unroll
            for (int nf = 0; nf < 4; nf++) {
                const uint32_t r0 = bbase + (uint32_t)((wn + nf * 8 + g) * SA + k0 + c);
                bf[nf][0] = Sw[r0];
                bf[nf][1] = Sw[r0 + 4];
            }
#pragma unroll
            for (int mf = 0; mf < 4; mf++)
#pragma unroll
                for (int nf = 0; nf < 4; nf++)
                    mma_f16(acc[mf][nf], af[mf], bf[nf]);
        }
        __syncthreads();
        if (++slot == NSTAGE) slot = 0;
        if (++fslot == NSTAGE) fslot = 0;
    }

    // ---- epilogue: per-row bias + (max, sumexp) over warp's 32 cols ----
    const int tn = blockIdx.y * 8 + wni;
#pragma unroll
    for (int mf = 0; mf < 4; mf++) {
#pragma unroll
        for (int rh = 0; rh < 2; rh++) {
            const int row = m0 + wm + mf * 16 + g + rh * 8;
            float vals[8];
            float mx = -CUDART_INF_F;
#pragma unroll
            for (int nf = 0; nf < 4; nf++)
#pragma unroll
                for (int b = 0; b < 2; b++) {
                    const float v = acc[mf][nf][rh * 2 + b] + sbias[wn + nf * 8 + 2 * c + b];
                    vals[nf * 2 + b] = v;
                    mx = fmaxf(mx, v);
                }
            mx = fmaxf(mx, __shfl_xor_sync(0xffffffffu, mx, 1));
            mx = fmaxf(mx, __shfl_xor_sync(0xffffffffu, mx, 2));
            float s = 0.f;
#pragma unroll
            for (int j = 0; j < 8; j++) s += __expf(vals[j] - mx);
            s += __shfl_xor_sync(0xffffffffu, s, 1);
            s += __shfl_xor_sync(0xffffffffu, s, 2);
            if (c == 0) {
                g_pmax[(size_t)row * NTN + tn] = mx;
                g_psum[(size_t)row * NTN + tn] = s;
            }
        }
    }
}

// ---------------- kernel 2: combine partials, per-token GRPO terms ----------------
__global__ void combine_kernel(const int* __restrict__ amask,
                               const float* __restrict__ adv,
                               const float* __restrict__ ref,
                               const float* __restrict__ oldlp,
                               float* __restrict__ out)
{
    const int warp = threadIdx.x >> 5;
    const int lane = threadIdx.x & 31;
    const int t = blockIdx.x * 8 + warp;
    if (t >= M_) return;

    const float* pm = g_pmax + (size_t)t * NTN;
    const float* ps = g_psum + (size_t)t * NTN;
    float M = -CUDART_INF_F;
    for (int j = lane; j < NTN; j += 32) M = fmaxf(M, pm[j]);
#pragma unroll
    for (int o = 16; o; o >>= 1) M = fmaxf(M, __shfl_xor_sync(0xffffffffu, M, o));
    float S = 0.f;
    for (int j = lane; j < NTN; j += 32) S += ps[j] * expf(pm[j] - M);
#pragma unroll
    for (int o = 16; o; o >>= 1) S += __shfl_xor_sync(0xffffffffu, S, o);

    if (lane == 0) {
        const float lse  = M + logf(S);
        const float logp = g_tok[t] - lse;
        out[1 + t] = logp;

        const float mask = (float)amask[t];
        const float a    = adv[t / T_];
        const float d    = ref[t] - logp;
        const float kl   = expf(d) - d - 1.f;
        const float c1   = expf(logp - oldlp[t]);
        const float c2   = fminf(fmaxf(c1, 0.8f), 1.2f);
        const float l1   = c1 * a, l2 = c2 * a;
        const float ptl  = -(fminf(l1, l2) - 0.04f * kl);
        g_losspt[t] = ptl * mask;
        g_klpt  [t] = kl  * mask;
        g_clippt[t] = (l1 < l2 ? 1.f : 0.f) * mask;
        g_maskpt[t] = mask;
    }
}

// ---------------- kernel 3: deterministic final reductions ----------------
__global__ void finalize_kernel(float* __restrict__ out, int out_size)
{
    __shared__ float sl[1024], sk[1024], sc[1024], sm[1024];
    const int t = threadIdx.x;
    float l = 0.f, k = 0.f, c = 0.f, m = 0.f;
    for (int i = t; i < M_; i += 1024) {
        l += g_losspt[i]; k += g_klpt[i]; c += g_clippt[i]; m += g_maskpt[i];
    }
    sl[t] = l; sk[t] = k; sc[t] = c; sm[t] = m;
    __syncthreads();
    for (int s = 512; s; s >>= 1) {
        if (t < s) { sl[t]+=sl[t+s]; sk[t]+=sk[t+s]; sc[t]+=sc[t+s]; sm[t]+=sm[t+s]; }
        __syncthreads();
    }
    if (t == 0) {
        out[0]      = sl[0] / sm[0];
        out[M_ + 1] = sk[0] / sm[0];
        out[M_ + 2] = sc[0] / sm[0];
    }
    for (int i = M_ + 3 + t; i < out_size; i += 1024) out[i] = 0.f;
}

// ---------------- launch ----------------
extern "C" void kernel_launch(void* const* d_in, const int* in_sizes, int n_in,
                              void* d_out, int out_size)
{
    const float* x     = (const float*)d_in[0];
    const float* w     = (const float*)d_in[1];
    const float* bias  = (const float*)d_in[2];
    const void*  ids   = d_in[3];
    const int*   amask = (const int*)d_in[4];
    const float* adv   = (const float*)d_in[5];
    const float* ref   = (const float*)d_in[6];
    const float* oldlp = (const float*)d_in[7];
    float* out = (float*)d_out;

    cudaFuncSetAttribute(gemm_lse_mma, cudaFuncAttributeMaxDynamicSharedMemorySize,
                         (int)SMEM_TOTAL);

    detect_id64_kernel<<<1, 256>>>((const int*)ids);

    // fp32 -> fp16 copies of W and X (device-global scratch)
    {
        __half* wh; cudaGetSymbolAddress((void**)&wh, g_Wh);
        __half* xh; cudaGetSymbolAddress((void**)&xh, g_Xh);
        const int wn8 = (V_ * H_) / 8, xn8 = (M_ * H_) / 8;
        convert_half_kernel<<<(wn8 + 511) / 512, 512>>>(w, wh, wn8);
        convert_half_kernel<<<(xn8 + 511) / 512, 512>>>(x, xh, xn8);
    }

    tok_logit_kernel<<<M_ / 8, 256>>>(x, w, bias, ids);

    dim3 grid(GRIDM, GRIDN);    // x fast -> consecutive CTAs share W tile in L2
    gemm_lse_mma<<<grid, 512, SMEM_TOTAL>>>(bias);

    combine_kernel<<<M_ / 8, 256>>>(amask, adv, ref, oldlp, out);
    finalize_kernel<<<1, 1024>>>(out, out_size);
}